// round 2
// baseline (speedup 1.0000x reference)
#include <cuda_runtime.h>
#include <cuda_bf16.h>

// FCOS loss: focal cls + centerness BCE + GIoU reg, fused.
// B=16, C=80, S=17064, levels hw = {12800,3200,800,208,56}.

#define BATCH 16
#define NCLS 80
#define STOT 17064
#define NCHUNK 69                 // 50+13+4+1+1 chunks of 256 positions
#define NBLK (BATCH * NCHUNK)     // 1104
#define ALPHA_F 0.25f

struct Ptrs {
    const float* cls[5];
    const float* cnt[5];
    const float* reg[5];
};

__device__ float g_cls[NBLK];
__device__ float g_cnt[NBLK];
__device__ float g_reg[NBLK];
__device__ float g_pos[NBLK];

__device__ __forceinline__ float wsum(float v) {
    #pragma unroll
    for (int o = 16; o; o >>= 1) v += __shfl_down_sync(0xffffffffu, v, o);
    return v;
}

__global__ __launch_bounds__(256) void k_main(
    Ptrs P,
    const float* __restrict__ cnt_t,
    const float* __restrict__ reg_t,
    const int* __restrict__ cls_t32)   // int32 view; may actually be int64 data
{
    int bid = blockIdx.x;
    int b = bid / NCHUNK;
    int chunk = bid - b * NCHUNK;

    int hw, sb, base, lvl;
    if (chunk < 50)      { hw = 12800; sb = 0;     base = chunk << 8;        lvl = 0; }
    else if (chunk < 63) { hw = 3200;  sb = 12800; base = (chunk - 50) << 8; lvl = 1; }
    else if (chunk < 67) { hw = 800;   sb = 16000; base = (chunk - 63) << 8; lvl = 2; }
    else if (chunk < 68) { hw = 208;   sb = 16800; base = 0;                 lvl = 3; }
    else                 { hw = 56;    sb = 17008; base = 0;                 lvl = 4; }

    int tid = threadIdx.x;
    int lane = tid & 31;

    // ---- dtype sniff: little-endian int64 has zero high-words at odd int32
    // indices. Targets are in [0,80]; 32 consecutive odd-index words all zero
    // is impossible for int32 data. Reads stay within first 64 words (safe
    // for either dtype: buffer >= 273024 words).
    int probe = cls_t32[2 * lane + 1];
    bool is64 = (__ballot_sync(0xffffffffu, probe != 0) == 0u);

    int pos = base + tid;
    bool valid = pos < hw;

    float a_cls = 0.f, a_cnt = 0.f, a_reg = 0.f, a_pos = 0.f;

    if (valid) {
        int s = sb + pos;
        size_t ti = (size_t)b * STOT + s;
        int tgt = is64 ? cls_t32[2 * ti] : cls_t32[ti];   // low word if int64
        float t = cnt_t[ti];

        if (t > -1.0f) {
            a_pos = 1.f;
            // ---- centerness BCE with logits ----
            float cv = P.cnt[lvl][(size_t)b * hw + pos];
            a_cnt = fmaxf(cv, 0.f) - cv * t + __logf(1.f + __expf(-fabsf(cv)));

            // ---- GIoU ----
            const float* rp = P.reg[lvl] + (size_t)b * 4 * hw + pos;
            float pl = rp[0], pt = rp[(size_t)hw], pr = rp[(size_t)2 * hw], pb = rp[(size_t)3 * hw];
            const float* rt = reg_t + ti * 4;
            float tl = rt[0], tt = rt[1], tr = rt[2], tb = rt[3];

            float wmin = fmaxf(fminf(pr, tr) + fminf(pl, tl), 0.f);
            float hmin = fmaxf(fminf(pb, tb) + fminf(pt, tt), 0.f);
            float ov  = wmin * hmin;
            float uni = (pr + pl) * (pb + pt) + (tr + tl) * (tb + tt) - ov;
            float wmax = fmaxf(fmaxf(pr, tr) + fmaxf(pl, tl), 0.f);
            float hmax = fmaxf(fmaxf(pb, tb) + fmaxf(pt, tt), 0.f);
            float ga = wmax * hmax;
            float giou = __fdividef(ov, uni) - __fdividef(ga - uni, fmaxf(ga, 1e-10f));
            a_reg = 1.f - giou;
        }

        // ---- focal classification loss over 80 channels ----
        // match (tgt == c+1):  alpha * sigmoid(-x)^2 * softplus(-x)
        // no match:        (1-alpha) * sigmoid( x)^2 * softplus( x)
        const float* cp = P.cls[lvl] + (size_t)b * NCLS * hw + pos;
        #pragma unroll 4
        for (int c = 0; c < NCLS; c++) {
            float x = __ldg(cp + (size_t)c * hw);
            bool m = (tgt == c + 1);
            float y = m ? -x : x;
            float a = m ? ALPHA_F : (1.f - ALPHA_F);
            float e = __expf(y);          // EX2
            float u = 1.f + e;
            float sp = __logf(u);         // LG2  = softplus(y)
            float sg = __fdividef(e, u);  // RCP  = sigmoid(y)
            a_cls = fmaf(a * sp, sg * sg, a_cls);
        }
    }

    // ---- block reduction (deterministic: per-block slot, no atomics) ----
    a_cls = wsum(a_cls); a_cnt = wsum(a_cnt); a_reg = wsum(a_reg); a_pos = wsum(a_pos);

    __shared__ float sm[8][4];
    int w = tid >> 5;
    if (lane == 0) { sm[w][0] = a_cls; sm[w][1] = a_cnt; sm[w][2] = a_reg; sm[w][3] = a_pos; }
    __syncthreads();
    if (w == 0 && lane < 8) {
        float v0 = sm[lane][0], v1 = sm[lane][1], v2 = sm[lane][2], v3 = sm[lane][3];
        #pragma unroll
        for (int o = 4; o; o >>= 1) {
            v0 += __shfl_down_sync(0xffu, v0, o);
            v1 += __shfl_down_sync(0xffu, v1, o);
            v2 += __shfl_down_sync(0xffu, v2, o);
            v3 += __shfl_down_sync(0xffu, v3, o);
        }
        if (lane == 0) {
            g_cls[bid] = v0; g_cnt[bid] = v1; g_reg[bid] = v2; g_pos[bid] = v3;
        }
    }
}

__global__ void k_final(float* __restrict__ out) {
    int lane = threadIdx.x;
    float cls = 0.f, cnt = 0.f, reg = 0.f, pos = 0.f;
    if (lane < BATCH) {
        int base = lane * NCHUNK;
        for (int c = 0; c < NCHUNK; c++) {
            cls += g_cls[base + c];
            cnt += g_cnt[base + c];
            reg += g_reg[base + c];
            pos += g_pos[base + c];
        }
        float np = fmaxf(pos, 1.f);
        cls /= np; cnt /= np; reg /= np;
    }
    #pragma unroll
    for (int o = 16; o; o >>= 1) {
        cls += __shfl_down_sync(0xffffffffu, cls, o);
        cnt += __shfl_down_sync(0xffffffffu, cnt, o);
        reg += __shfl_down_sync(0xffffffffu, reg, o);
    }
    if (lane == 0) {
        cls *= (1.f / BATCH);
        cnt *= (1.f / BATCH);
        reg *= (1.f / BATCH);
        out[0] = cls;
        out[1] = cnt;
        out[2] = reg;
        out[3] = cls + cnt + reg;
    }
}

extern "C" void kernel_launch(void* const* d_in, const int* in_sizes, int n_in,
                              void* d_out, int out_size)
{
    // Three candidate input orderings, disambiguated by element counts:
    //  interleaved (dict):    [cls_p0, cnt_p0, reg_p0, cls_p1, ...] -> in_sizes[1]=204800
    //  alphabetical (names):  [cls_p0..4, cls_targets, cnt_p0..4, cnt_targets,
    //                          reg_p0..4, reg_targets]             -> in_sizes[5]=273024
    //  grouped (signature):   [cls_p0..4, cnt_p0..4, reg_p0..4, cnt_t, reg_t, cls_t]
    Ptrs P;
    const float* cnt_t;
    const float* reg_t;
    const int*   cls_t;

    if (in_sizes[1] == 204800) {                    // interleaved
        for (int i = 0; i < 5; i++) {
            P.cls[i] = (const float*)d_in[3 * i + 0];
            P.cnt[i] = (const float*)d_in[3 * i + 1];
            P.reg[i] = (const float*)d_in[3 * i + 2];
        }
        cnt_t = (const float*)d_in[15];
        reg_t = (const float*)d_in[16];
        cls_t = (const int*)d_in[17];
    } else if (in_sizes[5] == 273024) {             // alphabetical
        for (int i = 0; i < 5; i++) {
            P.cls[i] = (const float*)d_in[i];
            P.cnt[i] = (const float*)d_in[6 + i];
            P.reg[i] = (const float*)d_in[12 + i];
        }
        cls_t = (const int*)d_in[5];
        cnt_t = (const float*)d_in[11];
        reg_t = (const float*)d_in[17];
    } else {                                        // grouped (signature order)
        for (int i = 0; i < 5; i++) {
            P.cls[i] = (const float*)d_in[i];
            P.cnt[i] = (const float*)d_in[5 + i];
            P.reg[i] = (const float*)d_in[10 + i];
        }
        cnt_t = (const float*)d_in[15];
        reg_t = (const float*)d_in[16];
        cls_t = (const int*)d_in[17];
    }

    k_main<<<NBLK, 256>>>(P, cnt_t, reg_t, cls_t);
    k_final<<<1, 32>>>((float*)d_out);
}

// round 3
// speedup vs baseline: 1.6144x; 1.6144x over previous
#include <cuda_runtime.h>
#include <cuda_bf16.h>

// FCOS loss: focal cls + centerness BCE + GIoU reg, fully fused single kernel.
// B=16, C=80, S=17064, levels hw = {12800,3200,800,208,56}.

#define BATCH 16
#define NCLS 80
#define STOT 17064
#define NCHUNK 36                 // 25+7+2+1+1 chunks of 512 positions
#define NBLK (BATCH * NCHUNK)     // 576 blocks -> 3.9/SM, single wave at occ>=4
#define C_NM 0.5198603854199589f  // 0.75 * ln2   (non-match weight, log2 domain)
#define C_M  0.17328679513998632f // 0.25 * ln2   (match weight)
#define L2E  1.4426950408889634f

struct Ptrs {
    const float* cls[5];
    const float* cnt[5];
    const float* reg[5];
};

__device__ float g_cls[NBLK];
__device__ float g_cnt[NBLK];
__device__ float g_reg[NBLK];
__device__ float g_pos[NBLK];
__device__ int   g_sem;           // zero-init; reset by last block each call

__device__ __forceinline__ float wsum(float v) {
    #pragma unroll
    for (int o = 16; o; o >>= 1) v += __shfl_down_sync(0xffffffffu, v, o);
    return v;
}

// sp2(x) * sigmoid(x)^2, sp2 = log2(1+e^x). Multiply by a*ln2 for focal term.
__device__ __forceinline__ float focal_core(float x) {
    float e  = exp2f(x * L2E);        // MUFU.EX2 (= e^x)
    float u  = 1.f + e;
    float sp = __log2f(u);            // MUFU.LG2
    float sg = __fdividef(e, u);      // MUFU.RCP + FMUL
    return sp * sg * sg;
}

__global__ __launch_bounds__(256) void k_main(
    Ptrs P,
    const float* __restrict__ cnt_t,
    const float* __restrict__ reg_t,
    const int* __restrict__ cls_t32,   // int32 view; may actually be int64 data
    float* __restrict__ out)
{
    int bid = blockIdx.x;
    int b = bid / NCHUNK;
    int chunk = bid - b * NCHUNK;

    int hw, sb, base, lvl;
    if (chunk < 25)      { hw = 12800; sb = 0;     base = chunk << 9;        lvl = 0; }
    else if (chunk < 32) { hw = 3200;  sb = 12800; base = (chunk - 25) << 9; lvl = 1; }
    else if (chunk < 34) { hw = 800;   sb = 16000; base = (chunk - 32) << 9; lvl = 2; }
    else if (chunk < 35) { hw = 208;   sb = 16800; base = 0;                 lvl = 3; }
    else                 { hw = 56;    sb = 17008; base = 0;                 lvl = 4; }

    int tid = threadIdx.x;
    int lane = tid & 31;

    // ---- dtype sniff: little-endian int64 -> odd int32 words are high words = 0.
    // Targets in [0,80]; 32 odd-index words all zero is impossible for int32 data.
    int probe = cls_t32[2 * lane + 1];
    bool is64 = (__ballot_sync(0xffffffffu, probe != 0) == 0u);

    int p0 = base + tid;
    int p1 = p0 + 256;
    bool v0 = p0 < hw;
    bool v1 = p1 < hw;
    int p0c = v0 ? p0 : 0;
    int p1c = v1 ? p1 : 0;

    float a_cnt = 0.f, a_reg = 0.f, a_pos = 0.f;
    int tgt0 = 0, tgt1 = 0;

    // ---- per-position scalar losses (cnt BCE + GIoU) ----
    #pragma unroll
    for (int k = 0; k < 2; k++) {
        int p = k ? p1 : p0;
        if (p >= hw) continue;
        size_t ti = (size_t)b * STOT + sb + p;
        int tgt = is64 ? cls_t32[2 * ti] : cls_t32[ti];
        if (k) tgt1 = tgt; else tgt0 = tgt;
        float t = cnt_t[ti];
        if (t > -1.0f) {
            a_pos += 1.f;
            float cv = P.cnt[lvl][(size_t)b * hw + p];
            a_cnt += fmaxf(cv, 0.f) - cv * t + __logf(1.f + __expf(-fabsf(cv)));

            const float* rp = P.reg[lvl] + (size_t)b * 4 * hw + p;
            float pl = rp[0], pt = rp[(size_t)hw], pr = rp[(size_t)2 * hw], pb = rp[(size_t)3 * hw];
            float4 rt = *reinterpret_cast<const float4*>(reg_t + ti * 4);
            float tl = rt.x, tt = rt.y, tr = rt.z, tb = rt.w;

            float wmin = fmaxf(fminf(pr, tr) + fminf(pl, tl), 0.f);
            float hmin = fmaxf(fminf(pb, tb) + fminf(pt, tt), 0.f);
            float ov  = wmin * hmin;
            float uni = (pr + pl) * (pb + pt) + (tr + tl) * (tb + tt) - ov;
            float wmax = fmaxf(fmaxf(pr, tr) + fmaxf(pl, tl), 0.f);
            float hmax = fmaxf(fmaxf(pb, tb) + fmaxf(pt, tt), 0.f);
            float ga = wmax * hmax;
            float giou = __fdividef(ov, uni) - __fdividef(ga - uni, fmaxf(ga, 1e-10f));
            a_reg += 1.f - giou;
        }
    }

    // ---- focal cls: branch-free non-match loop over 80 channels, 2 positions ----
    const float* cb = P.cls[lvl] + (size_t)b * NCLS * hw;
    const float* cp0 = cb + p0c;
    const float* cp1 = cb + p1c;
    float acc0 = 0.f, acc1 = 0.f;
    #pragma unroll 4
    for (int c = 0; c < NCLS; c++) {
        size_t off = (size_t)c * hw;
        acc0 = fmaf(C_NM, focal_core(__ldg(cp0 + off)), acc0);
        acc1 = fmaf(C_NM, focal_core(__ldg(cp1 + off)), acc1);
    }
    // fixup for the single matched channel (tgt in 1..80)
    if (v0 && (unsigned)(tgt0 - 1) < NCLS) {
        float x = __ldg(cp0 + (size_t)(tgt0 - 1) * hw);
        acc0 += C_M * focal_core(-x) - C_NM * focal_core(x);
    }
    if (v1 && (unsigned)(tgt1 - 1) < NCLS) {
        float x = __ldg(cp1 + (size_t)(tgt1 - 1) * hw);
        acc1 += C_M * focal_core(-x) - C_NM * focal_core(x);
    }
    float a_cls = (v0 ? acc0 : 0.f) + (v1 ? acc1 : 0.f);

    // ---- block reduction into per-block slots (deterministic) ----
    a_cls = wsum(a_cls); a_cnt = wsum(a_cnt); a_reg = wsum(a_reg); a_pos = wsum(a_pos);

    __shared__ float sm[8][4];
    int w = tid >> 5;
    if (lane == 0) { sm[w][0] = a_cls; sm[w][1] = a_cnt; sm[w][2] = a_reg; sm[w][3] = a_pos; }
    __syncthreads();
    if (w == 0 && lane < 8) {
        float x0 = sm[lane][0], x1 = sm[lane][1], x2 = sm[lane][2], x3 = sm[lane][3];
        #pragma unroll
        for (int o = 4; o; o >>= 1) {
            x0 += __shfl_down_sync(0xffu, x0, o);
            x1 += __shfl_down_sync(0xffu, x1, o);
            x2 += __shfl_down_sync(0xffu, x2, o);
            x3 += __shfl_down_sync(0xffu, x3, o);
        }
        if (lane == 0) {
            g_cls[bid] = x0; g_cnt[bid] = x1; g_reg[bid] = x2; g_pos[bid] = x3;
        }
    }

    // ---- last block finishes: parallel final combine (replaces k_final) ----
    __shared__ bool is_last;
    __threadfence();
    if (tid == 0) is_last = (atomicAdd(&g_sem, 1) == NBLK - 1);
    __syncthreads();
    if (!is_last) return;

    int bt = tid >> 4;       // batch 0..15
    int j  = tid & 15;
    float cls = 0.f, cnt = 0.f, reg = 0.f, pos = 0.f;
    for (int c = j; c < NCHUNK; c += 16) {
        int i = bt * NCHUNK + c;
        cls += g_cls[i]; cnt += g_cnt[i]; reg += g_reg[i]; pos += g_pos[i];
    }
    #pragma unroll
    for (int o = 8; o; o >>= 1) {
        cls += __shfl_down_sync(0xffffffffu, cls, o, 16);
        cnt += __shfl_down_sync(0xffffffffu, cnt, o, 16);
        reg += __shfl_down_sync(0xffffffffu, reg, o, 16);
        pos += __shfl_down_sync(0xffffffffu, pos, o, 16);
    }
    __shared__ float s3[16][3];
    if (j == 0) {
        float np = fmaxf(pos, 1.f);
        s3[bt][0] = cls / np; s3[bt][1] = cnt / np; s3[bt][2] = reg / np;
    }
    __syncthreads();
    if (tid < 16) {
        float c0 = s3[tid][0], c1 = s3[tid][1], c2 = s3[tid][2];
        #pragma unroll
        for (int o = 8; o; o >>= 1) {
            c0 += __shfl_down_sync(0xffffu, c0, o, 16);
            c1 += __shfl_down_sync(0xffffu, c1, o, 16);
            c2 += __shfl_down_sync(0xffffu, c2, o, 16);
        }
        if (tid == 0) {
            c0 *= (1.f / BATCH); c1 *= (1.f / BATCH); c2 *= (1.f / BATCH);
            out[0] = c0; out[1] = c1; out[2] = c2; out[3] = c0 + c1 + c2;
            g_sem = 0;   // reset for next graph replay
        }
    }
}

extern "C" void kernel_launch(void* const* d_in, const int* in_sizes, int n_in,
                              void* d_out, int out_size)
{
    // Three candidate input orderings, disambiguated by element counts:
    //  interleaved (dict):    in_sizes[1] = cnt_p0 = 204800
    //  alphabetical (names):  in_sizes[5] = cls_targets = 273024
    //  grouped (signature):   otherwise
    Ptrs P;
    const float* cnt_t;
    const float* reg_t;
    const int*   cls_t;

    if (in_sizes[1] == 204800) {                    // interleaved
        for (int i = 0; i < 5; i++) {
            P.cls[i] = (const float*)d_in[3 * i + 0];
            P.cnt[i] = (const float*)d_in[3 * i + 1];
            P.reg[i] = (const float*)d_in[3 * i + 2];
        }
        cnt_t = (const float*)d_in[15];
        reg_t = (const float*)d_in[16];
        cls_t = (const int*)d_in[17];
    } else if (in_sizes[5] == 273024) {             // alphabetical
        for (int i = 0; i < 5; i++) {
            P.cls[i] = (const float*)d_in[i];
            P.cnt[i] = (const float*)d_in[6 + i];
            P.reg[i] = (const float*)d_in[12 + i];
        }
        cls_t = (const int*)d_in[5];
        cnt_t = (const float*)d_in[11];
        reg_t = (const float*)d_in[17];
    } else {                                        // grouped (signature order)
        for (int i = 0; i < 5; i++) {
            P.cls[i] = (const float*)d_in[i];
            P.cnt[i] = (const float*)d_in[5 + i];
            P.reg[i] = (const float*)d_in[10 + i];
        }
        cnt_t = (const float*)d_in[15];
        reg_t = (const float*)d_in[16];
        cls_t = (const int*)d_in[17];
    }

    k_main<<<NBLK, 256>>>(P, cnt_t, reg_t, cls_t, (float*)d_out);
}

// round 4
// speedup vs baseline: 1.6380x; 1.0146x over previous
#include <cuda_runtime.h>
#include <cuda_bf16.h>

// FCOS loss: focal cls + centerness BCE + GIoU reg, fully fused single kernel.
// B=16, C=80, S=17064, levels hw = {12800,3200,800,208,56}.

#define BATCH 16
#define NCLS 80
#define STOT 17064
#define NCHUNK 36                 // 25+7+2+1+1 chunks of 512 positions
#define NBLK (BATCH * NCHUNK)     // 576 blocks, single wave at 4 blocks/SM
#define C_NM 0.5198603854199589f  // 0.75 * ln2   (non-match weight, log2 domain)
#define C_M  0.17328679513998632f // 0.25 * ln2   (match weight)
#define L2E  1.4426950408889634f
#define LN2  0.6931471805599453f

struct Ptrs {
    const float* cls[5];
    const float* cnt[5];
    const float* reg[5];
};

__device__ float g_cls[NBLK];
__device__ float g_cnt[NBLK];
__device__ float g_reg[NBLK];
__device__ float g_pos[NBLK];
__device__ int   g_sem;           // zero-init; reset by last block each call

__device__ __forceinline__ float wsum(float v) {
    #pragma unroll
    for (int o = 16; o; o >>= 1) v += __shfl_down_sync(0xffffffffu, v, o);
    return v;
}

// log2(1+e^x) * sigmoid(x)^2  (multiply by a*ln2 outside for focal term)
__device__ __forceinline__ float focal_core(float x) {
    float e  = exp2f(x * L2E);        // MUFU.EX2
    float u  = 1.f + e;
    float sp = __log2f(u);            // MUFU.LG2
    float sg = __fdividef(e, u);      // MUFU.RCP + FMUL
    return sp * (sg * sg);
}

// per-position GIoU loss (1 - giou)
__device__ __forceinline__ float giou_loss(float pl, float pt, float pr, float pb,
                                           float tl, float tt, float tr, float tb) {
    float wmin = fmaxf(fminf(pr, tr) + fminf(pl, tl), 0.f);
    float hmin = fmaxf(fminf(pb, tb) + fminf(pt, tt), 0.f);
    float ov   = wmin * hmin;
    float uni  = (pr + pl) * (pb + pt) + (tr + tl) * (tb + tt) - ov;
    float wmax = fmaxf(fmaxf(pr, tr) + fmaxf(pl, tl), 0.f);
    float hmax = fmaxf(fmaxf(pb, tb) + fmaxf(pt, tt), 0.f);
    float ga   = wmax * hmax;
    return 1.f - __fdividef(ov, uni) + __fdividef(ga - uni, fmaxf(ga, 1e-10f));
}

// BCE with logits
__device__ __forceinline__ float bce(float cv, float t) {
    float e = exp2f(-fabsf(cv) * L2E);
    return fmaxf(cv, 0.f) - cv * t + LN2 * __log2f(1.f + e);
}

__global__ __launch_bounds__(256) void k_main(
    Ptrs P,
    const float* __restrict__ cnt_t,
    const float* __restrict__ reg_t,
    const int* __restrict__ cls_t32,   // int32 view; may actually be int64 data
    float* __restrict__ out)
{
    int bid = blockIdx.x;
    int b = bid / NCHUNK;
    int chunk = bid - b * NCHUNK;

    int hw, sb, base, lvl;
    if (chunk < 25)      { hw = 12800; sb = 0;     base = chunk << 9;        lvl = 0; }
    else if (chunk < 32) { hw = 3200;  sb = 12800; base = (chunk - 25) << 9; lvl = 1; }
    else if (chunk < 34) { hw = 800;   sb = 16000; base = (chunk - 32) << 9; lvl = 2; }
    else if (chunk < 35) { hw = 208;   sb = 16800; base = 0;                 lvl = 3; }
    else                 { hw = 56;    sb = 17008; base = 0;                 lvl = 4; }

    int tid = threadIdx.x;
    int lane = tid & 31;

    // ---- dtype sniff: little-endian int64 -> odd int32 words (high words) are 0.
    // Targets in [0,80]; 32 odd-index words all zero is impossible for int32 data.
    int probe = cls_t32[2 * lane + 1];
    bool is64 = (__ballot_sync(0xffffffffu, probe != 0) == 0u);

    // each thread owns an adjacent position pair (hw is always even)
    int p0 = base + 2 * tid;
    bool v = p0 < hw;
    int p0c = v ? p0 : 0;

    size_t ti = (size_t)b * STOT + sb + p0c;     // even
    int hw2 = hw >> 1;

    // ---- targets for the pair ----
    int tgt0, tgt1;
    if (is64) {
        int4 tw = __ldg(reinterpret_cast<const int4*>(cls_t32 + 2 * ti));
        tgt0 = tw.x; tgt1 = tw.z;
    } else {
        int2 tw = __ldg(reinterpret_cast<const int2*>(cls_t32 + ti));
        tgt0 = tw.x; tgt1 = tw.y;
    }
    float2 ct = __ldg(reinterpret_cast<const float2*>(cnt_t + ti));

    float a_cnt = 0.f, a_reg = 0.f, a_pos = 0.f;

    if (v) {
        bool m0 = ct.x > -1.0f;
        bool m1 = ct.y > -1.0f;
        a_pos = (m0 ? 1.f : 0.f) + (m1 ? 1.f : 0.f);

        // centerness preds (pair)
        float2 cv = __ldg(reinterpret_cast<const float2*>(
                          P.cnt[lvl] + (size_t)b * hw + p0c));
        // reg preds (pair, 4 strided rows) + reg targets (2x float4)
        const float2* rp2 = reinterpret_cast<const float2*>(
                            P.reg[lvl] + (size_t)b * 4 * hw + p0c);
        float2 L = __ldg(rp2);
        float2 T = __ldg(rp2 + hw2);
        float2 R = __ldg(rp2 + 2 * hw2);
        float2 Bo = __ldg(rp2 + 3 * hw2);
        float4 rt0 = __ldg(reinterpret_cast<const float4*>(reg_t + ti * 4));
        float4 rt1 = __ldg(reinterpret_cast<const float4*>(reg_t + ti * 4 + 4));

        if (m0) {
            a_cnt += bce(cv.x, ct.x);
            a_reg += giou_loss(L.x, T.x, R.x, Bo.x, rt0.x, rt0.y, rt0.z, rt0.w);
        }
        if (m1) {
            a_cnt += bce(cv.y, ct.y);
            a_reg += giou_loss(L.y, T.y, R.y, Bo.y, rt1.x, rt1.y, rt1.z, rt1.w);
        }
    }

    // ---- focal cls: branch-free loop over 80 channels, float2 position pair ----
    const float* cb = P.cls[lvl] + (size_t)b * NCLS * hw;
    const float2* q = reinterpret_cast<const float2*>(cb + p0c);
    float acc0 = 0.f, acc1 = 0.f;
    #pragma unroll 4
    for (int c = 0; c < NCLS; c++) {
        float2 xv = __ldg(q);
        q += hw2;
        acc0 += focal_core(xv.x);
        acc1 += focal_core(xv.y);
    }
    float a_cls = C_NM * (acc0 + acc1);
    // fixup for the single matched channel per position (tgt in 1..80)
    if ((unsigned)(tgt0 - 1) < NCLS) {
        float x = __ldg(cb + (size_t)(tgt0 - 1) * hw + p0c);
        a_cls += C_M * focal_core(-x) - C_NM * focal_core(x);
    }
    if ((unsigned)(tgt1 - 1) < NCLS) {
        float x = __ldg(cb + (size_t)(tgt1 - 1) * hw + p0c + 1);
        a_cls += C_M * focal_core(-x) - C_NM * focal_core(x);
    }
    if (!v) a_cls = 0.f;

    // ---- block reduction into per-block slots (deterministic) ----
    a_cls = wsum(a_cls); a_cnt = wsum(a_cnt); a_reg = wsum(a_reg); a_pos = wsum(a_pos);

    __shared__ float sm[8][4];
    int w = tid >> 5;
    if (lane == 0) { sm[w][0] = a_cls; sm[w][1] = a_cnt; sm[w][2] = a_reg; sm[w][3] = a_pos; }
    __syncthreads();
    if (w == 0 && lane < 8) {
        float x0 = sm[lane][0], x1 = sm[lane][1], x2 = sm[lane][2], x3 = sm[lane][3];
        #pragma unroll
        for (int o = 4; o; o >>= 1) {
            x0 += __shfl_down_sync(0xffu, x0, o);
            x1 += __shfl_down_sync(0xffu, x1, o);
            x2 += __shfl_down_sync(0xffu, x2, o);
            x3 += __shfl_down_sync(0xffu, x3, o);
        }
        if (lane == 0) {
            g_cls[bid] = x0; g_cnt[bid] = x1; g_reg[bid] = x2; g_pos[bid] = x3;
        }
    }

    // ---- last block finishes: parallel final combine ----
    __shared__ bool is_last;
    __threadfence();
    if (tid == 0) is_last = (atomicAdd(&g_sem, 1) == NBLK - 1);
    __syncthreads();
    if (!is_last) return;

    int bt = tid >> 4;       // batch 0..15
    int j  = tid & 15;
    float cls = 0.f, cnt = 0.f, reg = 0.f, pos = 0.f;
    for (int c = j; c < NCHUNK; c += 16) {
        int i = bt * NCHUNK + c;
        cls += g_cls[i]; cnt += g_cnt[i]; reg += g_reg[i]; pos += g_pos[i];
    }
    #pragma unroll
    for (int o = 8; o; o >>= 1) {
        cls += __shfl_down_sync(0xffffffffu, cls, o, 16);
        cnt += __shfl_down_sync(0xffffffffu, cnt, o, 16);
        reg += __shfl_down_sync(0xffffffffu, reg, o, 16);
        pos += __shfl_down_sync(0xffffffffu, pos, o, 16);
    }
    __shared__ float s3[16][3];
    if (j == 0) {
        float np = fmaxf(pos, 1.f);
        s3[bt][0] = cls / np; s3[bt][1] = cnt / np; s3[bt][2] = reg / np;
    }
    __syncthreads();
    if (tid < 16) {
        float c0 = s3[tid][0], c1 = s3[tid][1], c2 = s3[tid][2];
        #pragma unroll
        for (int o = 8; o; o >>= 1) {
            c0 += __shfl_down_sync(0xffffu, c0, o, 16);
            c1 += __shfl_down_sync(0xffffu, c1, o, 16);
            c2 += __shfl_down_sync(0xffffu, c2, o, 16);
        }
        if (tid == 0) {
            c0 *= (1.f / BATCH); c1 *= (1.f / BATCH); c2 *= (1.f / BATCH);
            out[0] = c0; out[1] = c1; out[2] = c2; out[3] = c0 + c1 + c2;
            g_sem = 0;   // reset for next graph replay
        }
    }
}

extern "C" void kernel_launch(void* const* d_in, const int* in_sizes, int n_in,
                              void* d_out, int out_size)
{
    // Three candidate input orderings, disambiguated by element counts:
    //  interleaved (dict):    in_sizes[1] = cnt_p0 = 204800
    //  alphabetical (names):  in_sizes[5] = cls_targets = 273024
    //  grouped (signature):   otherwise
    Ptrs P;
    const float* cnt_t;
    const float* reg_t;
    const int*   cls_t;

    if (in_sizes[1] == 204800) {                    // interleaved
        for (int i = 0; i < 5; i++) {
            P.cls[i] = (const float*)d_in[3 * i + 0];
            P.cnt[i] = (const float*)d_in[3 * i + 1];
            P.reg[i] = (const float*)d_in[3 * i + 2];
        }
        cnt_t = (const float*)d_in[15];
        reg_t = (const float*)d_in[16];
        cls_t = (const int*)d_in[17];
    } else if (in_sizes[5] == 273024) {             // alphabetical
        for (int i = 0; i < 5; i++) {
            P.cls[i] = (const float*)d_in[i];
            P.cnt[i] = (const float*)d_in[6 + i];
            P.reg[i] = (const float*)d_in[12 + i];
        }
        cls_t = (const int*)d_in[5];
        cnt_t = (const float*)d_in[11];
        reg_t = (const float*)d_in[17];
    } else {                                        // grouped (signature order)
        for (int i = 0; i < 5; i++) {
            P.cls[i] = (const float*)d_in[i];
            P.cnt[i] = (const float*)d_in[5 + i];
            P.reg[i] = (const float*)d_in[10 + i];
        }
        cnt_t = (const float*)d_in[15];
        reg_t = (const float*)d_in[16];
        cls_t = (const int*)d_in[17];
    }

    k_main<<<NBLK, 256>>>(P, cnt_t, reg_t, cls_t, (float*)d_out);
}

// round 5
// speedup vs baseline: 1.7221x; 1.0513x over previous
#include <cuda_runtime.h>
#include <cuda_bf16.h>

// FCOS loss: focal cls + centerness BCE + GIoU reg, fully fused single kernel.
// B=16, C=80, S=17064, levels hw = {12800,3200,800,208,56}.

#define BATCH 16
#define NCLS 80
#define STOT 17064
#define NCHUNK 36                 // 25+7+2+1+1 chunks of 512 positions
#define NBLK (BATCH * NCHUNK)     // 576 blocks, single wave
#define C_NM 0.5198603854199589f  // 0.75 * ln2   (non-match weight, log2 domain)
#define C_M  0.17328679513998632f // 0.25 * ln2   (match weight)
#define L2E  1.4426950408889634f
#define LN2  0.6931471805599453f

struct Ptrs {
    const float* cls[5];
    const float* cnt[5];
    const float* reg[5];
};

__device__ float g_cls[NBLK];
__device__ float g_cnt[NBLK];
__device__ float g_reg[NBLK];
__device__ float g_pos[NBLK];
__device__ int   g_sem;           // zero-init; reset by last block each call

__device__ __forceinline__ float wsum(float v) {
    #pragma unroll
    for (int o = 16; o; o >>= 1) v += __shfl_down_sync(0xffffffffu, v, o);
    return v;
}

// log2(1+e^x) * sigmoid(x)^2 accumulated into acc (caller scales by a*ln2)
__device__ __forceinline__ void focal_acc(float x, float& acc) {
    float e  = exp2f(x * L2E);        // MUFU.EX2
    float u  = 1.f + e;
    float sp = __log2f(u);            // MUFU.LG2
    float sg = __fdividef(e, u);      // MUFU.RCP + FMUL
    acc = fmaf(sp, sg * sg, acc);
}

__device__ __forceinline__ float focal_one(float x) {
    float a = 0.f; focal_acc(x, a); return a;
}

// per-position GIoU loss (1 - giou)
__device__ __forceinline__ float giou_loss(float pl, float pt, float pr, float pb,
                                           float tl, float tt, float tr, float tb) {
    float wmin = fmaxf(fminf(pr, tr) + fminf(pl, tl), 0.f);
    float hmin = fmaxf(fminf(pb, tb) + fminf(pt, tt), 0.f);
    float ov   = wmin * hmin;
    float uni  = (pr + pl) * (pb + pt) + (tr + tl) * (tb + tt) - ov;
    float wmax = fmaxf(fmaxf(pr, tr) + fmaxf(pl, tl), 0.f);
    float hmax = fmaxf(fmaxf(pb, tb) + fmaxf(pt, tt), 0.f);
    float ga   = wmax * hmax;
    return 1.f - __fdividef(ov, uni) + __fdividef(ga - uni, fmaxf(ga, 1e-10f));
}

// BCE with logits
__device__ __forceinline__ float bce(float cv, float t) {
    float e = exp2f(-fabsf(cv) * L2E);
    return fmaxf(cv, 0.f) - cv * t + LN2 * __log2f(1.f + e);
}

__global__ __launch_bounds__(256) void k_main(
    Ptrs P,
    const float* __restrict__ cnt_t,
    const float* __restrict__ reg_t,
    const int* __restrict__ cls_t32,   // int32 view; may actually be int64 data
    float* __restrict__ out)
{
    int bid = blockIdx.x;
    int b = bid / NCHUNK;
    int chunk = bid - b * NCHUNK;

    int hw, sb, base, lvl;
    if (chunk < 25)      { hw = 12800; sb = 0;     base = chunk << 9;        lvl = 0; }
    else if (chunk < 32) { hw = 3200;  sb = 12800; base = (chunk - 25) << 9; lvl = 1; }
    else if (chunk < 34) { hw = 800;   sb = 16000; base = (chunk - 32) << 9; lvl = 2; }
    else if (chunk < 35) { hw = 208;   sb = 16800; base = 0;                 lvl = 3; }
    else                 { hw = 56;    sb = 17008; base = 0;                 lvl = 4; }

    int tid = threadIdx.x;
    int lane = tid & 31;

    // ---- dtype sniff: little-endian int64 -> odd int32 words (high words) are 0.
    int probe = cls_t32[2 * lane + 1];
    bool is64 = (__ballot_sync(0xffffffffu, probe != 0) == 0u);

    // each thread owns an adjacent position pair (hw is always even)
    int p0 = base + 2 * tid;
    bool v = p0 < hw;
    int p0c = v ? p0 : 0;

    size_t ti = (size_t)b * STOT + sb + p0c;     // even
    int hw2 = hw >> 1;

    // ---- targets for the pair ----
    int tgt0, tgt1;
    if (is64) {
        int4 tw = __ldg(reinterpret_cast<const int4*>(cls_t32 + 2 * ti));
        tgt0 = tw.x; tgt1 = tw.z;
    } else {
        int2 tw = __ldg(reinterpret_cast<const int2*>(cls_t32 + ti));
        tgt0 = tw.x; tgt1 = tw.y;
    }
    float2 ct = __ldg(reinterpret_cast<const float2*>(cnt_t + ti));

    float a_cnt = 0.f, a_reg = 0.f, a_pos = 0.f;

    if (v) {
        bool m0 = ct.x > -1.0f;
        bool m1 = ct.y > -1.0f;
        a_pos = (m0 ? 1.f : 0.f) + (m1 ? 1.f : 0.f);

        float2 cv = __ldg(reinterpret_cast<const float2*>(
                          P.cnt[lvl] + (size_t)b * hw + p0c));
        const float2* rp2 = reinterpret_cast<const float2*>(
                            P.reg[lvl] + (size_t)b * 4 * hw + p0c);
        float2 L = __ldg(rp2);
        float2 T = __ldg(rp2 + hw2);
        float2 R = __ldg(rp2 + 2 * hw2);
        float2 Bo = __ldg(rp2 + 3 * hw2);
        float4 rt0 = __ldg(reinterpret_cast<const float4*>(reg_t + ti * 4));
        float4 rt1 = __ldg(reinterpret_cast<const float4*>(reg_t + ti * 4 + 4));

        if (m0) {
            a_cnt += bce(cv.x, ct.x);
            a_reg += giou_loss(L.x, T.x, R.x, Bo.x, rt0.x, rt0.y, rt0.z, rt0.w);
        }
        if (m1) {
            a_cnt += bce(cv.y, ct.y);
            a_reg += giou_loss(L.y, T.y, R.y, Bo.y, rt1.x, rt1.y, rt1.z, rt1.w);
        }
    }

    // ---- focal cls: software-pipelined loop, 80 channels in 10 batches of 8 ----
    // Double-buffered: loads for batch k+1 issue before compute of batch k,
    // keeping 8 x LDG.64 in flight during each compute phase (MLP 8).
    const float* cb = P.cls[lvl] + (size_t)b * NCLS * hw;
    const float2* q = reinterpret_cast<const float2*>(cb + p0c);

    float2 bufA[8], bufB[8];
    float ac0 = 0.f, ac1 = 0.f, ac2 = 0.f, ac3 = 0.f;

    #pragma unroll
    for (int i = 0; i < 8; i++) bufA[i] = __ldg(q + (size_t)i * hw2);

    #pragma unroll
    for (int g = 0; g < 5; g++) {
        const float2* qb = q + (size_t)(16 * g + 8) * hw2;
        #pragma unroll
        for (int i = 0; i < 8; i++) bufB[i] = __ldg(qb + (size_t)i * hw2);
        #pragma unroll
        for (int i = 0; i < 8; i++) {
            focal_acc(bufA[i].x, (i & 1) ? ac2 : ac0);
            focal_acc(bufA[i].y, (i & 1) ? ac3 : ac1);
        }
        if (g < 4) {
            const float2* qa = q + (size_t)(16 * g + 16) * hw2;
            #pragma unroll
            for (int i = 0; i < 8; i++) bufA[i] = __ldg(qa + (size_t)i * hw2);
        }
        #pragma unroll
        for (int i = 0; i < 8; i++) {
            focal_acc(bufB[i].x, (i & 1) ? ac2 : ac0);
            focal_acc(bufB[i].y, (i & 1) ? ac3 : ac1);
        }
    }
    float a_cls = C_NM * ((ac0 + ac1) + (ac2 + ac3));

    // fixup for the single matched channel per position (tgt in 1..80)
    if ((unsigned)(tgt0 - 1) < NCLS) {
        float x = __ldg(cb + (size_t)(tgt0 - 1) * hw + p0c);
        a_cls += C_M * focal_one(-x) - C_NM * focal_one(x);
    }
    if ((unsigned)(tgt1 - 1) < NCLS) {
        float x = __ldg(cb + (size_t)(tgt1 - 1) * hw + p0c + 1);
        a_cls += C_M * focal_one(-x) - C_NM * focal_one(x);
    }
    if (!v) a_cls = 0.f;

    // ---- block reduction into per-block slots (deterministic) ----
    a_cls = wsum(a_cls); a_cnt = wsum(a_cnt); a_reg = wsum(a_reg); a_pos = wsum(a_pos);

    __shared__ float sm[8][4];
    int w = tid >> 5;
    if (lane == 0) { sm[w][0] = a_cls; sm[w][1] = a_cnt; sm[w][2] = a_reg; sm[w][3] = a_pos; }
    __syncthreads();
    if (w == 0 && lane < 8) {
        float x0 = sm[lane][0], x1 = sm[lane][1], x2 = sm[lane][2], x3 = sm[lane][3];
        #pragma unroll
        for (int o = 4; o; o >>= 1) {
            x0 += __shfl_down_sync(0xffu, x0, o);
            x1 += __shfl_down_sync(0xffu, x1, o);
            x2 += __shfl_down_sync(0xffu, x2, o);
            x3 += __shfl_down_sync(0xffu, x3, o);
        }
        if (lane == 0) {
            g_cls[bid] = x0; g_cnt[bid] = x1; g_reg[bid] = x2; g_pos[bid] = x3;
        }
    }

    // ---- last block finishes: parallel final combine ----
    __shared__ bool is_last;
    __threadfence();
    if (tid == 0) is_last = (atomicAdd(&g_sem, 1) == NBLK - 1);
    __syncthreads();
    if (!is_last) return;

    int bt = tid >> 4;       // batch 0..15
    int j  = tid & 15;
    float cls = 0.f, cnt = 0.f, reg = 0.f, pos = 0.f;
    for (int c = j; c < NCHUNK; c += 16) {
        int i = bt * NCHUNK + c;
        cls += g_cls[i]; cnt += g_cnt[i]; reg += g_reg[i]; pos += g_pos[i];
    }
    #pragma unroll
    for (int o = 8; o; o >>= 1) {
        cls += __shfl_down_sync(0xffffffffu, cls, o, 16);
        cnt += __shfl_down_sync(0xffffffffu, cnt, o, 16);
        reg += __shfl_down_sync(0xffffffffu, reg, o, 16);
        pos += __shfl_down_sync(0xffffffffu, pos, o, 16);
    }
    __shared__ float s3[16][3];
    if (j == 0) {
        float np = fmaxf(pos, 1.f);
        s3[bt][0] = cls / np; s3[bt][1] = cnt / np; s3[bt][2] = reg / np;
    }
    __syncthreads();
    if (tid < 16) {
        float c0 = s3[tid][0], c1 = s3[tid][1], c2 = s3[tid][2];
        #pragma unroll
        for (int o = 8; o; o >>= 1) {
            c0 += __shfl_down_sync(0xffffu, c0, o, 16);
            c1 += __shfl_down_sync(0xffffu, c1, o, 16);
            c2 += __shfl_down_sync(0xffffu, c2, o, 16);
        }
        if (tid == 0) {
            c0 *= (1.f / BATCH); c1 *= (1.f / BATCH); c2 *= (1.f / BATCH);
            out[0] = c0; out[1] = c1; out[2] = c2; out[3] = c0 + c1 + c2;
            g_sem = 0;   // reset for next graph replay
        }
    }
}

extern "C" void kernel_launch(void* const* d_in, const int* in_sizes, int n_in,
                              void* d_out, int out_size)
{
    // Three candidate input orderings, disambiguated by element counts:
    //  interleaved (dict):    in_sizes[1] = cnt_p0 = 204800
    //  alphabetical (names):  in_sizes[5] = cls_targets = 273024
    //  grouped (signature):   otherwise
    Ptrs P;
    const float* cnt_t;
    const float* reg_t;
    const int*   cls_t;

    if (in_sizes[1] == 204800) {                    // interleaved
        for (int i = 0; i < 5; i++) {
            P.cls[i] = (const float*)d_in[3 * i + 0];
            P.cnt[i] = (const float*)d_in[3 * i + 1];
            P.reg[i] = (const float*)d_in[3 * i + 2];
        }
        cnt_t = (const float*)d_in[15];
        reg_t = (const float*)d_in[16];
        cls_t = (const int*)d_in[17];
    } else if (in_sizes[5] == 273024) {             // alphabetical
        for (int i = 0; i < 5; i++) {
            P.cls[i] = (const float*)d_in[i];
            P.cnt[i] = (const float*)d_in[6 + i];
            P.reg[i] = (const float*)d_in[12 + i];
        }
        cls_t = (const int*)d_in[5];
        cnt_t = (const float*)d_in[11];
        reg_t = (const float*)d_in[17];
    } else {                                        // grouped (signature order)
        for (int i = 0; i < 5; i++) {
            P.cls[i] = (const float*)d_in[i];
            P.cnt[i] = (const float*)d_in[5 + i];
            P.reg[i] = (const float*)d_in[10 + i];
        }
        cnt_t = (const float*)d_in[15];
        reg_t = (const float*)d_in[16];
        cls_t = (const int*)d_in[17];
    }

    k_main<<<NBLK, 256>>>(P, cnt_t, reg_t, cls_t, (float*)d_out);
}